// round 2
// baseline (speedup 1.0000x reference)
#include <cuda_runtime.h>
#include <cstdint>

typedef unsigned long long ull;

#define CL 512
#define CB 64
#define CD 512
#define CLB (CL*CB)

// ---------------- scratch (static device allocations only) ----------------
__device__ float g_bufA[CLB*CD];              // activations ping (64 MB)
__device__ float g_bufB[CLB*CD];              // activations pong (64 MB)
__device__ float g_gx[(size_t)CLB*3*CD];      // gate pre-activations (192 MB)
__device__ float g_c[2][CB*CD];               // recurrent state ping-pong
__device__ int   g_tok[CLB];
__device__ unsigned g_cnt[4];                 // per-batch-group barrier counters

// ---------------- f32x2 helpers ----------------
__device__ __forceinline__ ull pk(float x){ ull r; asm("mov.b64 %0, {%1, %1};" : "=l"(r) : "f"(x)); return r; }
__device__ __forceinline__ ull pk2(float a, float b){ ull r; asm("mov.b64 %0, {%1, %2};" : "=l"(r) : "f"(a), "f"(b)); return r; }
__device__ __forceinline__ ull f2fma(ull a, ull b, ull c){ ull d; asm("fma.rn.f32x2 %0, %1, %2, %3;" : "=l"(d) : "l"(a), "l"(b), "l"(c)); return d; }
__device__ __forceinline__ float2 up2(ull v){ float2 f; asm("mov.b64 {%0, %1}, %2;" : "=f"(f.x), "=f"(f.y) : "l"(v)); return f; }
__device__ __forceinline__ unsigned ldacq(const unsigned* p){
    unsigned v; asm volatile("ld.acquire.gpu.u32 %0, [%1];" : "=r"(v) : "l"(p) : "memory"); return v;
}
__device__ __forceinline__ float sigmoidf_(float x){ return 1.0f / (1.0f + __expf(-x)); }

// ---------------- prep: token dtype detect + convert, zero state ----------------
__global__ void prep_kernel(const int* __restrict__ xs32) {
    __shared__ unsigned s_nz;
    int tid = threadIdx.x;
    if (tid == 0) s_nz = 0u;
    __syncthreads();
    unsigned nz = 0u;
    for (int i = tid; i < 1024; i += blockDim.x) nz |= (unsigned)xs32[2*i + 1];
    if (nz) atomicOr(&s_nz, 1u);
    __syncthreads();
    bool is64 = (s_nz == 0u);   // all odd 32-bit words zero -> int64 tokens

    int stride = gridDim.x * blockDim.x;
    int gid = blockIdx.x * blockDim.x + tid;
    if (is64) {
        const long long* x64 = (const long long*)xs32;
        for (int i = gid; i < CLB; i += stride) g_tok[i] = (int)x64[i];
    } else {
        for (int i = gid; i < CLB; i += stride) g_tok[i] = xs32[i];
    }
    for (int i = gid; i < CB*CD; i += stride) g_c[0][i] = 0.0f;
    if (gid < 4) g_cnt[gid] = 0u;
}

// ---------------- embedding gather ----------------
__global__ void embed_kernel(const float* __restrict__ emb) {
    int row = blockIdx.x;
    int tok = g_tok[row];
    const float4* s = (const float4*)(emb + (size_t)tok * CD);
    float4* d = (float4*)(g_bufA + (size_t)row * CD);
    d[threadIdx.x] = s[threadIdx.x];
}

// ---------------- SGEMM (f32x2): C[32768,1536] = A[32768,512] @ W[512,1536] + bias ----------------
#define BM 128
#define BN 128
#define BK 16

__global__ __launch_bounds__(256, 2)
void gemm_kernel(const float* __restrict__ A, const float* __restrict__ W,
                 const float* __restrict__ bias, float* __restrict__ C) {
    __shared__ float As[BK][BM];
    __shared__ float Bs[BK][BN];

    int tid = threadIdx.x;
    int bn = blockIdx.x;          // 0..11
    int bm = blockIdx.y;          // 0..255

    int arow  = tid >> 2;         // 0..63
    int acol4 = (tid & 3) * 4;    // 0,4,8,12
    int brow  = tid >> 5;         // 0..7
    int bcol4 = (tid & 31) * 4;

    const float* Ab = A + (size_t)bm * BM * 512;
    const float* Wb = W + bn * BN;

    ull acc[8][4];
    #pragma unroll
    for (int i = 0; i < 8; i++)
        #pragma unroll
        for (int j2 = 0; j2 < 4; j2++) acc[i][j2] = 0ULL;

    int ty8 = (tid >> 4) * 8;
    int tx8 = (tid & 15) * 8;

    for (int kb = 0; kb < 512; kb += BK) {
        float4 a0 = *(const float4*)(Ab + (size_t)arow        * 512 + kb + acol4);
        float4 a1 = *(const float4*)(Ab + (size_t)(arow + 64) * 512 + kb + acol4);
        float4 b0 = *(const float4*)(Wb + (size_t)(kb + brow)     * 1536 + bcol4);
        float4 b1 = *(const float4*)(Wb + (size_t)(kb + brow + 8) * 1536 + bcol4);

        As[acol4+0][arow] = a0.x; As[acol4+1][arow] = a0.y;
        As[acol4+2][arow] = a0.z; As[acol4+3][arow] = a0.w;
        As[acol4+0][arow+64] = a1.x; As[acol4+1][arow+64] = a1.y;
        As[acol4+2][arow+64] = a1.z; As[acol4+3][arow+64] = a1.w;
        *(float4*)&Bs[brow][bcol4]   = b0;
        *(float4*)&Bs[brow+8][bcol4] = b1;
        __syncthreads();

        #pragma unroll
        for (int k = 0; k < BK; k++) {
            float4 m0 = *(const float4*)&As[k][ty8];
            float4 m1 = *(const float4*)&As[k][ty8 + 4];
            float4 n0 = *(const float4*)&Bs[k][tx8];
            float4 n1 = *(const float4*)&Bs[k][tx8 + 4];
            ull nn0 = pk2(n0.x, n0.y), nn1 = pk2(n0.z, n0.w);
            ull nn2 = pk2(n1.x, n1.y), nn3 = pk2(n1.z, n1.w);
            float mv[8] = {m0.x, m0.y, m0.z, m0.w, m1.x, m1.y, m1.z, m1.w};
            #pragma unroll
            for (int i = 0; i < 8; i++) {
                ull mm = pk(mv[i]);
                acc[i][0] = f2fma(mm, nn0, acc[i][0]);
                acc[i][1] = f2fma(mm, nn1, acc[i][1]);
                acc[i][2] = f2fma(mm, nn2, acc[i][2]);
                acc[i][3] = f2fma(mm, nn3, acc[i][3]);
            }
        }
        __syncthreads();
    }

    const float* bp = bias + bn * BN + tx8;
    float4 bv0 = *(const float4*)bp;
    float4 bv1 = *(const float4*)(bp + 4);
    #pragma unroll
    for (int i = 0; i < 8; i++) {
        float2 p0 = up2(acc[i][0]), p1 = up2(acc[i][1]);
        float2 p2 = up2(acc[i][2]), p3 = up2(acc[i][3]);
        float4 o0 = make_float4(p0.x + bv0.x, p0.y + bv0.y, p1.x + bv0.z, p1.y + bv0.w);
        float4 o1 = make_float4(p2.x + bv1.x, p2.y + bv1.y, p3.x + bv1.z, p3.y + bv1.w);
        size_t row = (size_t)bm * BM + ty8 + i;
        float4* cp = (float4*)(C + row * 1536 + bn * BN + tx8);
        cp[0] = o0; cp[1] = o1;
    }
}

// ---------------- recurrent scan ----------------
// 128 blocks = 4 batch-groups (16 batch rows each) x 32 d-groups (16 (i,f) pairs each).
// Wc slice resident in SMEM as interleaved (i,f) float2; per-batch-group software
// barrier per timestep; c state ping-pongs in global memory.
__global__ __launch_bounds__(128)
void scan_kernel(const float* __restrict__ x_in, const float* __restrict__ gx,
                 const float* __restrict__ Wc, float* __restrict__ h_out,
                 int rev, unsigned cnt_base) {
    extern __shared__ float smem[];
    float2* Ws = (float2*)smem;                 // [k*16 + j], k in [0,512), j in [0,16)
    float*  c_s = smem + 512 * 16 * 2;          // [rr*512 + k], rr in [0,16)

    int tid = threadIdx.x;
    int bg = blockIdx.x >> 5;      // 0..3
    int dg = blockIdx.x & 31;      // 0..31
    int r0 = bg * 16;
    int d0 = dg * 16;

    // load Wc slice: (i,f) interleaved
    for (int idx = tid; idx < 512 * 16; idx += 128) {
        int k = idx >> 4, j = idx & 15;
        Ws[idx] = make_float2(Wc[k * 1024 + d0 + j], Wc[k * 1024 + 512 + d0 + j]);
    }

    int j  = tid & 15;
    int rg = tid >> 4;             // 0..7
    int rl0 = rg * 2, rl1 = rg * 2 + 1;
    int b0 = r0 + rl0, b1 = r0 + rl1;
    int d  = d0 + j;

    const ull* WsU = (const ull*)Ws;
    unsigned cnt_t = cnt_base;

    for (int t = 0; t < 512; ++t) {
        int tt = rev ? (511 - t) : t;
        int p  = t & 1;

        size_t row0 = (size_t)tt * CB + b0;
        size_t row1 = (size_t)tt * CB + b1;
        // prefetch gate pre-activations + residual input (independent of c)
        float gi0 = gx[row0*1536 + d], gf0 = gx[row0*1536 + 512 + d], gc0 = gx[row0*1536 + 1024 + d];
        float gi1 = gx[row1*1536 + d], gf1 = gx[row1*1536 + 512 + d], gc1 = gx[row1*1536 + 1024 + d];
        float xv0 = x_in[row0*512 + d];
        float xv1 = x_in[row1*512 + d];

        // stage c rows for this batch-group into SMEM
        const float4* csrc = (const float4*)(g_c[p]) + (size_t)r0 * 128;
        float4* cdst = (float4*)c_s;
        #pragma unroll
        for (int idx = tid; idx < 16 * 128; idx += 128) cdst[idx] = csrc[idx];
        __syncthreads();

        ull a0 = 0ULL, a1 = 0ULL;
        const float4* c0v = (const float4*)(c_s + rl0 * 512);
        const float4* c1v = (const float4*)(c_s + rl1 * 512);
        #pragma unroll 4
        for (int kk = 0; kk < 128; ++kk) {
            float4 cA = c0v[kk];
            float4 cB = c1v[kk];
            int kb = kk * 64 + j;
            ull w0 = WsU[kb], w1 = WsU[kb + 16], w2 = WsU[kb + 32], w3 = WsU[kb + 48];
            a0 = f2fma(pk(cA.x), w0, a0); a1 = f2fma(pk(cB.x), w0, a1);
            a0 = f2fma(pk(cA.y), w1, a0); a1 = f2fma(pk(cB.y), w1, a1);
            a0 = f2fma(pk(cA.z), w2, a0); a1 = f2fma(pk(cB.z), w2, a1);
            a0 = f2fma(pk(cA.w), w3, a0); a1 = f2fma(pk(cB.w), w3, a1);
        }
        float2 pre0 = up2(a0), pre1 = up2(a1);

        {
            float iv = sigmoidf_(gi0 + pre0.x);
            float fv = sigmoidf_(gf0 + pre0.y);
            float cn = iv * gc0 + fv * c_s[rl0 * 512 + d];
            h_out[row0*512 + d] = tanhf(cn) + xv0;
            g_c[p ^ 1][b0 * 512 + d] = cn;
        }
        {
            float iv = sigmoidf_(gi1 + pre1.x);
            float fv = sigmoidf_(gf1 + pre1.y);
            float cn = iv * gc1 + fv * c_s[rl1 * 512 + d];
            h_out[row1*512 + d] = tanhf(cn) + xv1;
            g_c[p ^ 1][b1 * 512 + d] = cn;
        }

        // per-batch-group barrier (32 blocks per domain, all co-resident)
        __threadfence();
        __syncthreads();
        cnt_t += 32;
        if (tid == 0) {
            atomicAdd(&g_cnt[bg], 1u);
            while (ldacq(&g_cnt[bg]) < cnt_t) { }
        }
        __syncthreads();
    }
}

// ---------------- driver ----------------
extern "C" void kernel_launch(void* const* d_in, const int* in_sizes, int n_in,
                              void* d_out, int out_size) {
    const int*   xs   = (const int*)  d_in[0];
    const float* emb  = (const float*)d_in[1];
    const float* Wx   = (const float*)d_in[2];
    const float* Wc   = (const float*)d_in[3];
    const float* bias = (const float*)d_in[4];
    float* out = (float*)d_out;

    void *pA, *pB, *pG;
    cudaGetSymbolAddress(&pA, g_bufA);
    cudaGetSymbolAddress(&pB, g_bufB);
    cudaGetSymbolAddress(&pG, g_gx);
    float* bufA = (float*)pA;
    float* bufB = (float*)pB;
    float* gxp  = (float*)pG;

    static bool attr_set = false;
    if (!attr_set) {
        cudaFuncSetAttribute(scan_kernel, cudaFuncAttributeMaxDynamicSharedMemorySize, 98304);
        attr_set = true;
    }

    prep_kernel<<<128, 256>>>(xs);
    embed_kernel<<<CLB, 128>>>(emb);

    dim3 ggrid(12, 256);
    unsigned cnt = 0;
    const unsigned SCAN_TICKS = 32u * 512u;

    // layer 0 forward: bufA -> bufB
    gemm_kernel<<<ggrid, 256>>>(bufA, Wx + 0*512*1536, bias + 0*1536, gxp);
    scan_kernel<<<128, 128, 98304>>>(bufA, gxp, Wc + 0*512*1024, bufB, 0, cnt);
    cnt += SCAN_TICKS;
    // layer 0 backward: bufB -> bufA
    gemm_kernel<<<ggrid, 256>>>(bufB, Wx + 1*512*1536, bias + 1*1536, gxp);
    scan_kernel<<<128, 128, 98304>>>(bufB, gxp, Wc + 1*512*1024, bufA, 1, cnt);
    cnt += SCAN_TICKS;
    // layer 1 forward: bufA -> bufB
    gemm_kernel<<<ggrid, 256>>>(bufA, Wx + 2*512*1536, bias + 2*1536, gxp);
    scan_kernel<<<128, 128, 98304>>>(bufA, gxp, Wc + 2*512*1024, bufB, 0, cnt);
    cnt += SCAN_TICKS;
    // layer 1 backward: bufB -> out
    gemm_kernel<<<ggrid, 256>>>(bufB, Wx + 3*512*1536, bias + 3*1536, gxp);
    scan_kernel<<<128, 128, 98304>>>(bufB, gxp, Wc + 3*512*1024, out, 1, cnt);
}

// round 4
// speedup vs baseline: 1.4522x; 1.4522x over previous
#include <cuda_runtime.h>
#include <cstdint>

typedef unsigned long long ull;
typedef ulonglong2 ullv2;

#define CL 512
#define CB 64
#define CD 512
#define CLB (CL*CB)

// ---------------- scratch (static device allocations only) ----------------
__device__ float g_bufA[CLB*CD];              // activations ping (64 MB)
__device__ float g_bufB[CLB*CD];              // activations pong (64 MB)
__device__ float g_gx[(size_t)CLB*3*CD];      // gate pre-activations (192 MB)
__device__ float g_c[2][CB*CD];               // recurrent state ping-pong
__device__ int   g_tok[CLB];
__device__ unsigned g_cnt[4];                 // per-batch-group barrier counters

// ---------------- f32x2 helpers ----------------
__device__ __forceinline__ ull pk(float x){ ull r; asm("mov.b64 %0, {%1, %1};" : "=l"(r) : "f"(x)); return r; }
__device__ __forceinline__ ull pk2(float a, float b){ ull r; asm("mov.b64 %0, {%1, %2};" : "=l"(r) : "f"(a), "f"(b)); return r; }
__device__ __forceinline__ ull f2fma(ull a, ull b, ull c){ ull d; asm("fma.rn.f32x2 %0, %1, %2, %3;" : "=l"(d) : "l"(a), "l"(b), "l"(c)); return d; }
__device__ __forceinline__ ull f2add(ull a, ull b){ ull d; asm("add.rn.f32x2 %0, %1, %2;" : "=l"(d) : "l"(a), "l"(b)); return d; }
__device__ __forceinline__ float2 up2(ull v){ float2 f; asm("mov.b64 {%0, %1}, %2;" : "=f"(f.x), "=f"(f.y) : "l"(v)); return f; }
__device__ __forceinline__ unsigned ldacq(const unsigned* p){
    unsigned v; asm volatile("ld.acquire.gpu.u32 %0, [%1];" : "=r"(v) : "l"(p) : "memory"); return v;
}
__device__ __forceinline__ float sigmoidf_(float x){ return 1.0f / (1.0f + __expf(-x)); }

// ---------------- prep: token dtype detect + convert, zero state ----------------
__global__ void prep_kernel(const int* __restrict__ xs32) {
    __shared__ unsigned s_nz;
    int tid = threadIdx.x;
    if (tid == 0) s_nz = 0u;
    __syncthreads();
    unsigned nz = 0u;
    for (int i = tid; i < 1024; i += blockDim.x) nz |= (unsigned)xs32[2*i + 1];
    if (nz) atomicOr(&s_nz, 1u);
    __syncthreads();
    bool is64 = (s_nz == 0u);   // all odd 32-bit words zero -> int64 tokens

    int stride = gridDim.x * blockDim.x;
    int gid = blockIdx.x * blockDim.x + tid;
    if (is64) {
        const long long* x64 = (const long long*)xs32;
        for (int i = gid; i < CLB; i += stride) g_tok[i] = (int)x64[i];
    } else {
        for (int i = gid; i < CLB; i += stride) g_tok[i] = xs32[i];
    }
    for (int i = gid; i < CB*CD; i += stride) g_c[0][i] = 0.0f;
    if (gid < 4) g_cnt[gid] = 0u;
}

// ---------------- embedding gather ----------------
__global__ void embed_kernel(const float* __restrict__ emb) {
    int row = blockIdx.x;
    int tok = g_tok[row];
    const float4* s = (const float4*)(emb + (size_t)tok * CD);
    float4* d = (float4*)(g_bufA + (size_t)row * CD);
    d[threadIdx.x] = s[threadIdx.x];
}

// ---------------- SGEMM (f32x2): C[32768,1536] = A[32768,512] @ W[512,1536] + bias ----------------
#define BM 128
#define BN 128
#define BK 16

__global__ __launch_bounds__(256, 2)
void gemm_kernel(const float* __restrict__ A, const float* __restrict__ W,
                 const float* __restrict__ bias, float* __restrict__ C) {
    __shared__ float As[BK][BM];
    __shared__ float Bs[BK][BN];

    int tid = threadIdx.x;
    int bn = blockIdx.x;          // 0..11
    int bm = blockIdx.y;          // 0..255

    int arow  = tid >> 2;         // 0..63
    int acol4 = (tid & 3) * 4;    // 0,4,8,12
    int brow  = tid >> 5;         // 0..7
    int bcol4 = (tid & 31) * 4;

    const float* Ab = A + (size_t)bm * BM * 512;
    const float* Wb = W + bn * BN;

    ull acc[8][4];
    #pragma unroll
    for (int i = 0; i < 8; i++)
        #pragma unroll
        for (int j2 = 0; j2 < 4; j2++) acc[i][j2] = 0ULL;

    int ty8 = (tid >> 4) * 8;
    int tx8 = (tid & 15) * 8;

    for (int kb = 0; kb < 512; kb += BK) {
        float4 a0 = *(const float4*)(Ab + (size_t)arow        * 512 + kb + acol4);
        float4 a1 = *(const float4*)(Ab + (size_t)(arow + 64) * 512 + kb + acol4);
        float4 b0 = *(const float4*)(Wb + (size_t)(kb + brow)     * 1536 + bcol4);
        float4 b1 = *(const float4*)(Wb + (size_t)(kb + brow + 8) * 1536 + bcol4);

        As[acol4+0][arow] = a0.x; As[acol4+1][arow] = a0.y;
        As[acol4+2][arow] = a0.z; As[acol4+3][arow] = a0.w;
        As[acol4+0][arow+64] = a1.x; As[acol4+1][arow+64] = a1.y;
        As[acol4+2][arow+64] = a1.z; As[acol4+3][arow+64] = a1.w;
        *(float4*)&Bs[brow][bcol4]   = b0;
        *(float4*)&Bs[brow+8][bcol4] = b1;
        __syncthreads();

        #pragma unroll
        for (int k = 0; k < BK; k++) {
            float4 m0 = *(const float4*)&As[k][ty8];
            float4 m1 = *(const float4*)&As[k][ty8 + 4];
            float4 n0 = *(const float4*)&Bs[k][tx8];
            float4 n1 = *(const float4*)&Bs[k][tx8 + 4];
            ull nn0 = pk2(n0.x, n0.y), nn1 = pk2(n0.z, n0.w);
            ull nn2 = pk2(n1.x, n1.y), nn3 = pk2(n1.z, n1.w);
            float mv[8] = {m0.x, m0.y, m0.z, m0.w, m1.x, m1.y, m1.z, m1.w};
            #pragma unroll
            for (int i = 0; i < 8; i++) {
                ull mm = pk(mv[i]);
                acc[i][0] = f2fma(mm, nn0, acc[i][0]);
                acc[i][1] = f2fma(mm, nn1, acc[i][1]);
                acc[i][2] = f2fma(mm, nn2, acc[i][2]);
                acc[i][3] = f2fma(mm, nn3, acc[i][3]);
            }
        }
        __syncthreads();
    }

    const float* bp = bias + bn * BN + tx8;
    float4 bv0 = *(const float4*)bp;
    float4 bv1 = *(const float4*)(bp + 4);
    #pragma unroll
    for (int i = 0; i < 8; i++) {
        float2 p0 = up2(acc[i][0]), p1 = up2(acc[i][1]);
        float2 p2 = up2(acc[i][2]), p3 = up2(acc[i][3]);
        float4 o0 = make_float4(p0.x + bv0.x, p0.y + bv0.y, p1.x + bv0.z, p1.y + bv0.w);
        float4 o1 = make_float4(p2.x + bv1.x, p2.y + bv1.y, p3.x + bv1.z, p3.y + bv1.w);
        size_t row = (size_t)bm * BM + ty8 + i;
        float4* cp = (float4*)(C + row * 1536 + bn * BN + tx8);
        cp[0] = o0; cp[1] = o1;
    }
}

// ---------------- recurrent scan (v2: W in registers, k-pair fma2, SMEM reduce) ----------------
// 128 blocks = 4 batch-groups (16 rows) x 32 d-groups (16 (i,f) col pairs).
// 256 threads: matvec role (j = tid&15 column pair, kg = tid>>4 k-chunk of 32),
// epilogue role (erow = tid>>4, ej = tid&15 -> one output element).
// SMEM: c_s[16][512] floats (32KB) + red[16][272] ull (~34KB).
#define RED_OFF 8192          // float index where red[] starts (32KB)
#define SCAN_SMEM (32768 + 16*272*8)

__global__ __launch_bounds__(256, 1)
void scan_kernel(const float* __restrict__ x_in, const float* __restrict__ gx,
                 const float* __restrict__ Wc, float* __restrict__ h_out,
                 int rev, unsigned cnt_base) {
    extern __shared__ float smem[];
    float* c_s  = smem;                         // [row*512 + k]
    ull*   red  = (ull*)(smem + RED_OFF);       // [row*272 + j*17 + kg]

    int tid = threadIdx.x;
    int bg = blockIdx.x >> 5;      // 0..3
    int dg = blockIdx.x & 31;      // 0..31
    int r0 = bg * 16;
    int d0 = dg * 16;

    int j  = tid & 15;             // matvec column pair
    int kg = tid >> 4;             // matvec k-chunk (32 k's)
    int k0 = kg * 32;

    // W in registers: k-pair packed. wi[p] = (Wi_{k0+2p}, Wi_{k0+2p+1}), same for wf.
    ull wi[16], wf_[16];
    #pragma unroll
    for (int p = 0; p < 16; p++) {
        int k = k0 + 2*p;
        wi[p]  = pk2(Wc[(size_t)k * 1024 + d0 + j],       Wc[(size_t)(k+1) * 1024 + d0 + j]);
        wf_[p] = pk2(Wc[(size_t)k * 1024 + 512 + d0 + j], Wc[(size_t)(k+1) * 1024 + 512 + d0 + j]);
    }

    // epilogue mapping
    int erow = tid >> 4;
    int ej   = tid & 15;
    int eb   = r0 + erow;          // global batch row
    int ed   = d0 + ej;            // global d index

    unsigned cnt_t = cnt_base;

    for (int t = 0; t < 512; ++t) {
        int tt = rev ? (511 - t) : t;
        int p  = t & 1;

        // ---- prefetch gate pre-activations + residual input (independent of c)
        size_t grow = (size_t)tt * CB + eb;
        float gi = gx[grow*1536 + ed];
        float gf = gx[grow*1536 + 512 + ed];
        float gc = gx[grow*1536 + 1024 + ed];
        float xv = x_in[grow*512 + ed];

        // ---- stage c rows for this batch-group into SMEM (32KB from L2)
        {
            const float4* csrc = (const float4*)(g_c[p]) + (size_t)r0 * 128;
            float4* cdst = (float4*)c_s;
            #pragma unroll
            for (int it = 0; it < 8; it++) cdst[tid + it*256] = csrc[tid + it*256];
        }
        __syncthreads();

        // ---- matvec: part[row] = (sum_k c*Wi, sum_k c*Wf) over this thread's 32 k
        const ullv2* cu = (const ullv2*)c_s;   // 2 k-pairs per 16B
        #pragma unroll 4
        for (int row = 0; row < 16; ++row) {
            ull ai = 0ULL, af = 0ULL;
            int base = row * 128 + kg * 8;   // ullv2 units
            #pragma unroll
            for (int q = 0; q < 8; q++) {
                ullv2 v = cu[base + q];
                ai = f2fma(v.x, wi[2*q],   ai);
                af = f2fma(v.x, wf_[2*q],  af);
                ai = f2fma(v.y, wi[2*q+1], ai);
                af = f2fma(v.y, wf_[2*q+1], af);
            }
            float2 si = up2(ai), sf = up2(af);
            red[row * 272 + j * 17 + kg] = pk2(si.x + si.y, sf.x + sf.y);
        }
        __syncthreads();

        // ---- reduce 16 kg partials + epilogue (one output per thread)
        {
            const ull* rp = red + erow * 272 + ej * 17;
            ull s0 = f2add(rp[0], rp[1]);
            ull s1 = f2add(rp[2], rp[3]);
            ull s2 = f2add(rp[4], rp[5]);
            ull s3 = f2add(rp[6], rp[7]);
            ull s4 = f2add(rp[8], rp[9]);
            ull s5 = f2add(rp[10], rp[11]);
            ull s6 = f2add(rp[12], rp[13]);
            ull s7 = f2add(rp[14], rp[15]);
            s0 = f2add(s0, s1); s2 = f2add(s2, s3);
            s4 = f2add(s4, s5); s6 = f2add(s6, s7);
            s0 = f2add(s0, s2); s4 = f2add(s4, s6);
            s0 = f2add(s0, s4);
            float2 pre = up2(s0);

            float c_old = c_s[erow * 512 + ed];
            float iv = sigmoidf_(gi + pre.x);
            float fv = sigmoidf_(gf + pre.y);
            float cn = iv * gc + fv * c_old;
            h_out[grow*512 + ed] = tanhf(cn) + xv;
            g_c[p ^ 1][(size_t)eb * 512 + ed] = cn;
        }

        // ---- per-batch-group barrier (32 co-resident blocks per domain)
        __threadfence();
        __syncthreads();
        cnt_t += 32;
        if (tid == 0) {
            atomicAdd(&g_cnt[bg], 1u);
            while (ldacq(&g_cnt[bg]) < cnt_t) { }
        }
        __syncthreads();
    }
}

// ---------------- driver ----------------
extern "C" void kernel_launch(void* const* d_in, const int* in_sizes, int n_in,
                              void* d_out, int out_size) {
    const int*   xs   = (const int*)  d_in[0];
    const float* emb  = (const float*)d_in[1];
    const float* Wx   = (const float*)d_in[2];
    const float* Wc   = (const float*)d_in[3];
    const float* bias = (const float*)d_in[4];
    float* out = (float*)d_out;

    void *pA, *pB, *pG;
    cudaGetSymbolAddress(&pA, g_bufA);
    cudaGetSymbolAddress(&pB, g_bufB);
    cudaGetSymbolAddress(&pG, g_gx);
    float* bufA = (float*)pA;
    float* bufB = (float*)pB;
    float* gxp  = (float*)pG;

    static bool attr_set = false;
    if (!attr_set) {
        cudaFuncSetAttribute(scan_kernel, cudaFuncAttributeMaxDynamicSharedMemorySize, SCAN_SMEM);
        attr_set = true;
    }

    prep_kernel<<<128, 256>>>(xs);
    embed_kernel<<<CLB, 128>>>(emb);

    dim3 ggrid(12, 256);
    unsigned cnt = 0;
    const unsigned SCAN_TICKS = 32u * 512u;

    // layer 0 forward: bufA -> bufB
    gemm_kernel<<<ggrid, 256>>>(bufA, Wx + 0*512*1536, bias + 0*1536, gxp);
    scan_kernel<<<128, 256, SCAN_SMEM>>>(bufA, gxp, Wc + 0*512*1024, bufB, 0, cnt);
    cnt += SCAN_TICKS;
    // layer 0 backward: bufB -> bufA
    gemm_kernel<<<ggrid, 256>>>(bufB, Wx + 1*512*1536, bias + 1*1536, gxp);
    scan_kernel<<<128, 256, SCAN_SMEM>>>(bufB, gxp, Wc + 1*512*1024, bufA, 1, cnt);
    cnt += SCAN_TICKS;
    // layer 1 forward: bufA -> bufB
    gemm_kernel<<<ggrid, 256>>>(bufA, Wx + 2*512*1536, bias + 2*1536, gxp);
    scan_kernel<<<128, 256, SCAN_SMEM>>>(bufA, gxp, Wc + 2*512*1024, bufB, 0, cnt);
    cnt += SCAN_TICKS;
    // layer 1 backward: bufB -> out
    gemm_kernel<<<ggrid, 256>>>(bufB, Wx + 3*512*1536, bias + 3*1536, gxp);
    scan_kernel<<<128, 256, SCAN_SMEM>>>(bufB, gxp, Wc + 3*512*1024, out, 1, cnt);
}

// round 6
// speedup vs baseline: 1.8694x; 1.2873x over previous
#include <cuda_runtime.h>
#include <cuda_bf16.h>
#include <cstdint>

typedef unsigned long long ull;
typedef ulonglong2 ullv2;

#define CL 512
#define CB 64
#define CD 512
#define CLB (CL*CB)

// ---------------- scratch (static device allocations only) ----------------
__device__ float g_bufA[CLB*CD];              // activations ping (64 MB)
__device__ float g_bufB[CLB*CD];              // activations pong (64 MB)
__device__ float g_gx[(size_t)CLB*3*CD];      // gate pre-activations (192 MB)
__device__ float g_c[2][CB*CD];               // recurrent state ping-pong
__device__ int   g_tok[CLB];
__device__ unsigned g_cnt[4];                 // per-batch-group barrier counters
// bf16 split buffers
__device__ ull g_Ahi[(size_t)CLB*CD/4];       // [32768,512] bf16
__device__ ull g_Alo[(size_t)CLB*CD/4];
__device__ ull g_Wthi[(size_t)4*1536*512/4];  // [4][1536][512] bf16 (W transposed)
__device__ ull g_Wtlo[(size_t)4*1536*512/4];

// ---------------- f32x2 / misc helpers ----------------
__device__ __forceinline__ ull pk(float x){ ull r; asm("mov.b64 %0, {%1, %1};" : "=l"(r) : "f"(x)); return r; }
__device__ __forceinline__ ull pk2(float a, float b){ ull r; asm("mov.b64 %0, {%1, %2};" : "=l"(r) : "f"(a), "f"(b)); return r; }
__device__ __forceinline__ ull f2fma(ull a, ull b, ull c){ ull d; asm("fma.rn.f32x2 %0, %1, %2, %3;" : "=l"(d) : "l"(a), "l"(b), "l"(c)); return d; }
__device__ __forceinline__ ull f2add(ull a, ull b){ ull d; asm("add.rn.f32x2 %0, %1, %2;" : "=l"(d) : "l"(a), "l"(b)); return d; }
__device__ __forceinline__ float2 up2(ull v){ float2 f; asm("mov.b64 {%0, %1}, %2;" : "=f"(f.x), "=f"(f.y) : "l"(v)); return f; }
__device__ __forceinline__ unsigned ldacq(const unsigned* p){
    unsigned v; asm volatile("ld.acquire.gpu.u32 %0, [%1];" : "=r"(v) : "l"(p) : "memory"); return v;
}
__device__ __forceinline__ float sigmoidf_(float x){ return 1.0f / (1.0f + __expf(-x)); }

__device__ __forceinline__ uint32_t smem_u32(const void* p){
    uint32_t a; asm("{ .reg .u64 t; cvta.to.shared.u64 t, %1; cvt.u32.u64 %0, t; }" : "=r"(a) : "l"(p));
    return a;
}
__device__ __forceinline__ void cpasync16(uint32_t dst, const void* src){
    asm volatile("cp.async.cg.shared.global [%0], [%1], 16;" :: "r"(dst), "l"(src));
}
__device__ __forceinline__ void cp_commit(){ asm volatile("cp.async.commit_group;" ::: "memory"); }

__device__ __forceinline__ void ldsm4(uint32_t addr, uint32_t* r){
    asm volatile("ldmatrix.sync.aligned.m8n8.x4.shared.b16 {%0,%1,%2,%3}, [%4];"
        : "=r"(r[0]),"=r"(r[1]),"=r"(r[2]),"=r"(r[3]) : "r"(addr));
}
__device__ __forceinline__ void ldsm2(uint32_t addr, uint32_t* r){
    asm volatile("ldmatrix.sync.aligned.m8n8.x2.shared.b16 {%0,%1}, [%2];"
        : "=r"(r[0]),"=r"(r[1]) : "r"(addr));
}
__device__ __forceinline__ void mma16816(float* d, const uint32_t* a, const uint32_t* b){
    asm volatile("mma.sync.aligned.m16n8k16.row.col.f32.bf16.bf16.f32 "
        "{%0,%1,%2,%3}, {%4,%5,%6,%7}, {%8,%9}, {%0,%1,%2,%3};"
        : "+f"(d[0]),"+f"(d[1]),"+f"(d[2]),"+f"(d[3])
        : "r"(a[0]),"r"(a[1]),"r"(a[2]),"r"(a[3]), "r"(b[0]),"r"(b[1]));
}

// ---------------- prep: token dtype detect + convert, zero state ----------------
__global__ void prep_kernel(const int* __restrict__ xs32) {
    __shared__ unsigned s_nz;
    int tid = threadIdx.x;
    if (tid == 0) s_nz = 0u;
    __syncthreads();
    unsigned nz = 0u;
    for (int i = tid; i < 1024; i += blockDim.x) nz |= (unsigned)xs32[2*i + 1];
    if (nz) atomicOr(&s_nz, 1u);
    __syncthreads();
    bool is64 = (s_nz == 0u);

    int stride = gridDim.x * blockDim.x;
    int gid = blockIdx.x * blockDim.x + tid;
    if (is64) {
        const long long* x64 = (const long long*)xs32;
        for (int i = gid; i < CLB; i += stride) g_tok[i] = (int)x64[i];
    } else {
        for (int i = gid; i < CLB; i += stride) g_tok[i] = xs32[i];
    }
    for (int i = gid; i < CB*CD; i += stride) g_c[0][i] = 0.0f;
    if (gid < 4) g_cnt[gid] = 0u;
}

// ---------------- embedding gather ----------------
__global__ void embed_kernel(const float* __restrict__ emb) {
    int row = blockIdx.x;
    int tok = g_tok[row];
    const float4* s = (const float4*)(emb + (size_t)tok * CD);
    float4* d = (float4*)(g_bufA + (size_t)row * CD);
    d[threadIdx.x] = s[threadIdx.x];
}

// ---------------- W transpose + bf16 hi/lo split ----------------
__global__ void wsplit_kernel(const float* __restrict__ W) {
    __shared__ float t[32][33];
    int layer = blockIdx.z;
    int nt = blockIdx.x;     // 0..47
    int kt = blockIdx.y;     // 0..15
    int tx = threadIdx.x;    // 0..31
    __nv_bfloat16* Whi = (__nv_bfloat16*)g_Wthi;
    __nv_bfloat16* Wlo = (__nv_bfloat16*)g_Wtlo;
    for (int i = threadIdx.y; i < 32; i += 8)
        t[i][tx] = W[(size_t)layer*512*1536 + (size_t)(kt*32 + i)*1536 + nt*32 + tx];
    __syncthreads();
    for (int i = threadIdx.y; i < 32; i += 8) {
        float v = t[tx][i];
        __nv_bfloat16 h = __float2bfloat16(v);
        __nv_bfloat16 l = __float2bfloat16(v - __bfloat162float(h));
        size_t o = ((size_t)layer*1536 + nt*32 + i)*512 + kt*32 + tx;
        Whi[o] = h; Wlo[o] = l;
    }
}

// ---------------- A bf16 hi/lo split ----------------
__global__ void asplit_kernel(const float* __restrict__ A) {
    size_t i = (size_t)blockIdx.x * blockDim.x + threadIdx.x;   // float4 index
    float4 v = ((const float4*)A)[i];
    __nv_bfloat16 h0 = __float2bfloat16(v.x), h1 = __float2bfloat16(v.y);
    __nv_bfloat16 h2 = __float2bfloat16(v.z), h3 = __float2bfloat16(v.w);
    __nv_bfloat162* Hi = (__nv_bfloat162*)g_Ahi;
    __nv_bfloat162* Lo = (__nv_bfloat162*)g_Alo;
    Hi[2*i]   = __nv_bfloat162(h0, h1);
    Hi[2*i+1] = __nv_bfloat162(h2, h3);
    Lo[2*i]   = __nv_bfloat162(__float2bfloat16(v.x - __bfloat162float(h0)),
                               __float2bfloat16(v.y - __bfloat162float(h1)));
    Lo[2*i+1] = __nv_bfloat162(__float2bfloat16(v.z - __bfloat162float(h2)),
                               __float2bfloat16(v.w - __bfloat162float(h3)));
}

// ---------------- mma.sync GEMM: C[32768,1536] = A @ W + bias (3-term bf16 split) ----------------
#define STAGE    65536
#define O_AHI    0
#define O_ALO    16384
#define O_WHI    32768
#define O_WLO    49152
#define GEMM_SMEM (2*STAGE + 1024)

__device__ __forceinline__ void load_stage(uint32_t sbuf,
        const __nv_bfloat16* Ah, const __nv_bfloat16* Al,
        const __nv_bfloat16* Wh, const __nv_bfloat16* Wl, int kc, int tid) {
    #pragma unroll
    for (int it = 0; it < 4; it++) {
        int c = tid + it*256;          // 0..1023
        int row = c >> 3, seg = c & 7;
        uint32_t off = row*128 + seg*16;
        uint32_t sw  = off ^ ((off >> 3) & 0x70);
        size_t goff = (size_t)row*512 + kc*64 + seg*8;
        cpasync16(sbuf + O_AHI + sw, Ah + goff);
        cpasync16(sbuf + O_ALO + sw, Al + goff);
        cpasync16(sbuf + O_WHI + sw, Wh + goff);
        cpasync16(sbuf + O_WLO + sw, Wl + goff);
    }
}

__global__ __launch_bounds__(256, 1)
void mma_gemm_kernel(const float* __restrict__ bias, float* __restrict__ C, int layer) {
    extern __shared__ char gsm[];
    __shared__ float sbias[128];

    int tid = threadIdx.x;
    int lane = tid & 31;
    int warp = tid >> 5;
    int wm = warp >> 1;          // 0..3 -> rows wm*32..+31
    int wn = warp & 1;           // 0..1 -> cols wn*64..+63
    int bn = blockIdx.x;         // 0..11
    int bm = blockIdx.y;         // 0..255
    int m0 = bm * 128, n0 = bn * 128;

    uint32_t dynbase = (smem_u32(gsm) + 1023u) & ~1023u;

    const __nv_bfloat16* Ah = (const __nv_bfloat16*)g_Ahi + (size_t)m0 * 512;
    const __nv_bfloat16* Al = (const __nv_bfloat16*)g_Alo + (size_t)m0 * 512;
    const __nv_bfloat16* Wh = (const __nv_bfloat16*)g_Wthi + ((size_t)layer*1536 + n0) * 512;
    const __nv_bfloat16* Wl = (const __nv_bfloat16*)g_Wtlo + ((size_t)layer*1536 + n0) * 512;

    if (tid < 128) sbias[tid] = bias[n0 + tid];

    // ---- per-lane ldmatrix address prep (byte offsets within a 128x64 bf16 tile, SW128)
    // A x4: lanes: row = (lane&7) + ((lane>>3)&1)*8 ; kbyte extra = (lane>>4)*16
    int a_rowin = (lane & 7) + ((lane >> 3) & 1) * 8;
    uint32_t a_kb_lane = (uint32_t)(lane >> 4) * 16;
    uint32_t a_rowb[2]; uint32_t a_s[2];
    #pragma unroll
    for (int t = 0; t < 2; t++) {
        uint32_t rb = (uint32_t)(wm*32 + t*16 + a_rowin) * 128;
        a_rowb[t] = rb;
        a_s[t] = (rb >> 3) & 0x70;
    }
    // B x2: lanes 0-15 used: row n = bt*8 + (lane&7); kbyte extra = ((lane>>3)&1)*16
    int b_rowin = lane & 7;
    uint32_t b_kb_lane = (uint32_t)((lane >> 3) & 1) * 16;
    uint32_t b_rowb[8]; uint32_t b_s[8];
    #pragma unroll
    for (int bt = 0; bt < 8; bt++) {
        uint32_t rb = (uint32_t)(wn*64 + bt*8 + b_rowin) * 128;
        b_rowb[bt] = rb;
        b_s[bt] = (rb >> 3) & 0x70;
    }

    float acc[2][8][4];
    #pragma unroll
    for (int t = 0; t < 2; t++)
        #pragma unroll
        for (int bt = 0; bt < 8; bt++)
            #pragma unroll
            for (int q = 0; q < 4; q++) acc[t][bt][q] = 0.0f;

    load_stage(dynbase, Ah, Al, Wh, Wl, 0, tid);
    cp_commit();

    for (int kc = 0; kc < 8; kc++) {
        uint32_t cbuf = dynbase + (kc & 1) * STAGE;
        if (kc < 7) {
            load_stage(dynbase + ((kc + 1) & 1) * STAGE, Ah, Al, Wh, Wl, kc + 1, tid);
            cp_commit();
            asm volatile("cp.async.wait_group 1;" ::: "memory");
        } else {
            asm volatile("cp.async.wait_group 0;" ::: "memory");
        }
        __syncthreads();

        #pragma unroll
        for (int ks = 0; ks < 4; ks++) {
            uint32_t akb = (uint32_t)ks*32 + a_kb_lane;
            uint32_t bkb = (uint32_t)ks*32 + b_kb_lane;
            uint32_t ah[2][4], al[2][4];
            #pragma unroll
            for (int t = 0; t < 2; t++) {
                uint32_t ao = a_rowb[t] + (akb ^ a_s[t]);
                ldsm4(cbuf + O_AHI + ao, ah[t]);
                ldsm4(cbuf + O_ALO + ao, al[t]);
            }
            uint32_t bh[8][2], bl[8][2];
            #pragma unroll
            for (int bt = 0; bt < 8; bt++) {
                uint32_t bo = b_rowb[bt] + (bkb ^ b_s[bt]);
                ldsm2(cbuf + O_WHI + bo, bh[bt]);
                ldsm2(cbuf + O_WLO + bo, bl[bt]);
            }
            #pragma unroll
            for (int t = 0; t < 2; t++)
                #pragma unroll
                for (int bt = 0; bt < 8; bt++) {
                    mma16816(acc[t][bt], ah[t], bh[bt]);
                    mma16816(acc[t][bt], ah[t], bl[bt]);
                    mma16816(acc[t][bt], al[t], bh[bt]);
                }
        }
        __syncthreads();
    }

    // ---- epilogue: add bias, store fp32
    int r_in = lane >> 2;          // 0..7
    int c_in = 2 * (lane & 3);     // 0,2,4,6
    #pragma unroll
    for (int t = 0; t < 2; t++) {
        int row = m0 + wm*32 + t*16 + r_in;
        #pragma unroll
        for (int bt = 0; bt < 8; bt++) {
            int col = wn*64 + bt*8 + c_in;
            float b0 = sbias[col], b1 = sbias[col + 1];
            float2 o0 = make_float2(acc[t][bt][0] + b0, acc[t][bt][1] + b1);
            float2 o1 = make_float2(acc[t][bt][2] + b0, acc[t][bt][3] + b1);
            *(float2*)(C + (size_t)row * 1536 + n0 + col) = o0;
            *(float2*)(C + (size_t)(row + 8) * 1536 + n0 + col) = o1;
        }
    }
}

// ---------------- recurrent scan (unchanged from R4) ----------------
#define RED_OFF 8192
#define SCAN_SMEM (32768 + 16*272*8)

__global__ __launch_bounds__(256, 1)
void scan_kernel(const float* __restrict__ x_in, const float* __restrict__ gx,
                 const float* __restrict__ Wc, float* __restrict__ h_out,
                 int rev, unsigned cnt_base) {
    extern __shared__ float smem[];
    float* c_s  = smem;
    ull*   red  = (ull*)(smem + RED_OFF);

    int tid = threadIdx.x;
    int bg = blockIdx.x >> 5;
    int dg = blockIdx.x & 31;
    int r0 = bg * 16;
    int d0 = dg * 16;

    int j  = tid & 15;
    int kg = tid >> 4;
    int k0 = kg * 32;

    ull wi[16], wf_[16];
    #pragma unroll
    for (int p = 0; p < 16; p++) {
        int k = k0 + 2*p;
        wi[p]  = pk2(Wc[(size_t)k * 1024 + d0 + j],       Wc[(size_t)(k+1) * 1024 + d0 + j]);
        wf_[p] = pk2(Wc[(size_t)k * 1024 + 512 + d0 + j], Wc[(size_t)(k+1) * 1024 + 512 + d0 + j]);
    }

    int erow = tid >> 4;
    int ej   = tid & 15;
    int eb   = r0 + erow;
    int ed   = d0 + ej;

    unsigned cnt_t = cnt_base;

    for (int t = 0; t < 512; ++t) {
        int tt = rev ? (511 - t) : t;
        int p  = t & 1;

        size_t grow = (size_t)tt * CB + eb;
        float gi = gx[grow*1536 + ed];
        float gf = gx[grow*1536 + 512 + ed];
        float gc = gx[grow*1536 + 1024 + ed];
        float xv = x_in[grow*512 + ed];

        {
            const float4* csrc = (const float4*)(g_c[p]) + (size_t)r0 * 128;
            float4* cdst = (float4*)c_s;
            #pragma unroll
            for (int it = 0; it < 8; it++) cdst[tid + it*256] = csrc[tid + it*256];
        }
        __syncthreads();

        const ullv2* cu = (const ullv2*)c_s;
        #pragma unroll 4
        for (int row = 0; row < 16; ++row) {
            ull ai = 0ULL, af = 0ULL;
            int base = row * 128 + kg * 8;
            #pragma unroll
            for (int q = 0; q < 8; q++) {
                ullv2 v = cu[base + q];
                ai = f2fma(v.x, wi[2*q],   ai);
                af = f2fma(v.x, wf_[2*q],  af);
                ai = f2fma(v.y, wi[2*q+1], ai);
                af = f2fma(v.y, wf_[2*q+1], af);
            }
            float2 si = up2(ai), sf = up2(af);
            red[row * 272 + j * 17 + kg] = pk2(si.x + si.y, sf.x + sf.y);
        }
        __syncthreads();

        {
            const ull* rp = red + erow * 272 + ej * 17;
            ull s0 = f2add(rp[0], rp[1]);
            ull s1 = f2add(rp[2], rp[3]);
            ull s2 = f2add(rp[4], rp[5]);
            ull s3 = f2add(rp[6], rp[7]);
            ull s4 = f2add(rp[8], rp[9]);
            ull s5 = f2add(rp[10], rp[11]);
            ull s6 = f2add(rp[12], rp[13]);
            ull s7 = f2add(rp[14], rp[15]);
            s0 = f2add(s0, s1); s2 = f2add(s2, s3);
            s4 = f2add(s4, s5); s6 = f2add(s6, s7);
            s0 = f2add(s0, s2); s4 = f2add(s4, s6);
            s0 = f2add(s0, s4);
            float2 pre = up2(s0);

            float c_old = c_s[erow * 512 + ed];
            float iv = sigmoidf_(gi + pre.x);
            float fv = sigmoidf_(gf + pre.y);
            float cn = iv * gc + fv * c_old;
            h_out[grow*512 + ed] = tanhf(cn) + xv;
            g_c[p ^ 1][(size_t)eb * 512 + ed] = cn;
        }

        __threadfence();
        __syncthreads();
        cnt_t += 32;
        if (tid == 0) {
            atomicAdd(&g_cnt[bg], 1u);
            while (ldacq(&g_cnt[bg]) < cnt_t) { }
        }
        __syncthreads();
    }
}

// ---------------- driver ----------------
extern "C" void kernel_launch(void* const* d_in, const int* in_sizes, int n_in,
                              void* d_out, int out_size) {
    const int*   xs   = (const int*)  d_in[0];
    const float* emb  = (const float*)d_in[1];
    const float* Wx   = (const float*)d_in[2];
    const float* Wc   = (const float*)d_in[3];
    const float* bias = (const float*)d_in[4];
    float* out = (float*)d_out;

    void *pA, *pB, *pG;
    cudaGetSymbolAddress(&pA, g_bufA);
    cudaGetSymbolAddress(&pB, g_bufB);
    cudaGetSymbolAddress(&pG, g_gx);
    float* bufA = (float*)pA;
    float* bufB = (float*)pB;
    float* gxp  = (float*)pG;

    static bool attr_set = false;
    if (!attr_set) {
        cudaFuncSetAttribute(scan_kernel, cudaFuncAttributeMaxDynamicSharedMemorySize, SCAN_SMEM);
        cudaFuncSetAttribute(mma_gemm_kernel, cudaFuncAttributeMaxDynamicSharedMemorySize, GEMM_SMEM);
        attr_set = true;
    }

    prep_kernel<<<128, 256>>>(xs);
    embed_kernel<<<CLB, 128>>>(emb);
    wsplit_kernel<<<dim3(48, 16, 4), dim3(32, 8)>>>(Wx);

    dim3 ggrid(12, 256);
    unsigned cnt = 0;
    const unsigned SCAN_TICKS = 32u * 512u;

    // layer 0 forward: bufA -> bufB
    asplit_kernel<<<16384, 256>>>(bufA);
    mma_gemm_kernel<<<ggrid, 256, GEMM_SMEM>>>(bias + 0*1536, gxp, 0);
    scan_kernel<<<128, 256, SCAN_SMEM>>>(bufA, gxp, Wc + 0*512*1024, bufB, 0, cnt);
    cnt += SCAN_TICKS;
    // layer 0 backward: bufB -> bufA
    asplit_kernel<<<16384, 256>>>(bufB);
    mma_gemm_kernel<<<ggrid, 256, GEMM_SMEM>>>(bias + 1*1536, gxp, 1);
    scan_kernel<<<128, 256, SCAN_SMEM>>>(bufB, gxp, Wc + 1*512*1024, bufA, 1, cnt);
    cnt += SCAN_TICKS;
    // layer 1 forward: bufA -> bufB
    asplit_kernel<<<16384, 256>>>(bufA);
    mma_gemm_kernel<<<ggrid, 256, GEMM_SMEM>>>(bias + 2*1536, gxp, 2);
    scan_kernel<<<128, 256, SCAN_SMEM>>>(bufA, gxp, Wc + 2*512*1024, bufB, 0, cnt);
    cnt += SCAN_TICKS;
    // layer 1 backward: bufB -> out
    asplit_kernel<<<16384, 256>>>(bufB);
    mma_gemm_kernel<<<ggrid, 256, GEMM_SMEM>>>(bias + 3*1536, gxp, 3);
    scan_kernel<<<128, 256, SCAN_SMEM>>>(bufB, gxp, Wc + 3*512*1024, out, 1, cnt);
}